// round 15
// baseline (speedup 1.0000x reference)
#include <cuda_runtime.h>

// out[n, i] = b[n, i] * sum_j a[n, j],  B = L = 8192, fp32.
// FINAL (locked): fused, one CTA per row, 256 threads, plain cached accesses,
// single-barrier reduction, 8 CTAs/SM (regs=32), 256-bit (v8.f32) loads and
// stores in both phases.
// Measured twice: 110.6us kernel, 86.6% DRAM, ~6860 GB/s — the HBM3e
// 2-read:1-write-mix ceiling for this 768MB stream on sm_103a. All other
// axes (cache hints, smem staging, cp.async, split kernels, persistence,
// block shape, rows/CTA) measured neutral or worse over 14 rounds.

constexpr int L = 8192;
constexpr int THREADS = 256;
constexpr int NWARPS = THREADS / 32;            // 8
constexpr int V8_PER_ROW = L / 8;               // 1024 float8 per row
constexpr int V8PT = V8_PER_ROW / THREADS;      // 4 float8 per thread

__device__ __forceinline__ void ldg_v8(const float* p, float r[8]) {
    asm volatile("ld.global.v8.f32 {%0,%1,%2,%3,%4,%5,%6,%7}, [%8];"
                 : "=f"(r[0]), "=f"(r[1]), "=f"(r[2]), "=f"(r[3]),
                   "=f"(r[4]), "=f"(r[5]), "=f"(r[6]), "=f"(r[7])
                 : "l"(p));
}

__device__ __forceinline__ void stg_v8(float* p, const float r[8]) {
    asm volatile("st.global.v8.f32 [%0], {%1,%2,%3,%4,%5,%6,%7,%8};"
                 :: "l"(p),
                    "f"(r[0]), "f"(r[1]), "f"(r[2]), "f"(r[3]),
                    "f"(r[4]), "f"(r[5]), "f"(r[6]), "f"(r[7])
                 : "memory");
}

__global__ __launch_bounds__(THREADS, 8)
void outer_product_rowscale(const float* __restrict__ a,
                            const float* __restrict__ b,
                            float* __restrict__ out)
{
    __shared__ float warp_sums[NWARPS];

    const int row = blockIdx.x;
    const int tid = threadIdx.x;

    const float* aR = a   + (size_t)row * L;
    const float* bR = b   + (size_t)row * L;
    float*       oR = out + (size_t)row * L;

    // ---- Phase 1: row-sum of a with 256-bit loads ----
    float s0 = 0.f, s1 = 0.f, s2 = 0.f, s3 = 0.f;
    #pragma unroll
    for (int i = 0; i < V8PT; i++) {
        float r[8];
        ldg_v8(aR + (tid + i * THREADS) * 8, r);
        s0 += r[0] + r[4];
        s1 += r[1] + r[5];
        s2 += r[2] + r[6];
        s3 += r[3] + r[7];
    }
    float s = (s0 + s1) + (s2 + s3);

    // warp reduce (xor: full sum in every lane)
    #pragma unroll
    for (int off = 16; off > 0; off >>= 1)
        s += __shfl_xor_sync(0xFFFFFFFFu, s, off);

    if ((tid & 31) == 0) warp_sums[tid >> 5] = s;
    __syncthreads();                             // single barrier

    // Every thread sums the 8 partials (broadcast LDS.128, conflict-free).
    const float4 w0 = *reinterpret_cast<const float4*>(&warp_sums[0]);
    const float4 w1 = *reinterpret_cast<const float4*>(&warp_sums[4]);
    const float scale = ((w0.x + w0.y) + (w0.z + w0.w))
                      + ((w1.x + w1.y) + (w1.z + w1.w));

    // ---- Phase 2: out = b * scale with 256-bit accesses ----
    #pragma unroll
    for (int i = 0; i < V8PT; i++) {
        const int idx = (tid + i * THREADS) * 8;
        float r[8];
        ldg_v8(bR + idx, r);
        #pragma unroll
        for (int k = 0; k < 8; k++) r[k] *= scale;
        stg_v8(oR + idx, r);
    }
}

extern "C" void kernel_launch(void* const* d_in, const int* in_sizes, int n_in,
                              void* d_out, int out_size)
{
    const float* a = (const float*)d_in[0];
    const float* b = (const float*)d_in[1];
    float* out = (float*)d_out;

    const int rows = in_sizes[0] / L;            // 8192
    outer_product_rowscale<<<rows, THREADS>>>(a, b, out);
}

// round 16
// speedup vs baseline: 1.0120x; 1.0120x over previous
#include <cuda_runtime.h>

// out[n, i] = b[n, i] * sum_j a[n, j],  B = L = 8192, fp32.
// R11 body with 512-thread CTAs: 4 CTAs/SM (still 64 warps), only 4
// concurrent row-streams per SM -> fewer open HBM address streams, testing
// the stream-locality mechanism suggested by the 128t regression (R12).
// v8.f32 accesses both phases, plain cached, single-barrier reduction.

constexpr int L = 8192;
constexpr int THREADS = 512;
constexpr int NWARPS = THREADS / 32;            // 16
constexpr int V8_PER_ROW = L / 8;               // 1024 float8 per row
constexpr int V8PT = V8_PER_ROW / THREADS;      // 2 float8 per thread

__device__ __forceinline__ void ldg_v8(const float* p, float r[8]) {
    asm volatile("ld.global.v8.f32 {%0,%1,%2,%3,%4,%5,%6,%7}, [%8];"
                 : "=f"(r[0]), "=f"(r[1]), "=f"(r[2]), "=f"(r[3]),
                   "=f"(r[4]), "=f"(r[5]), "=f"(r[6]), "=f"(r[7])
                 : "l"(p));
}

__device__ __forceinline__ void stg_v8(float* p, const float r[8]) {
    asm volatile("st.global.v8.f32 [%0], {%1,%2,%3,%4,%5,%6,%7,%8};"
                 :: "l"(p),
                    "f"(r[0]), "f"(r[1]), "f"(r[2]), "f"(r[3]),
                    "f"(r[4]), "f"(r[5]), "f"(r[6]), "f"(r[7])
                 : "memory");
}

__global__ __launch_bounds__(THREADS, 4)
void outer_product_rowscale(const float* __restrict__ a,
                            const float* __restrict__ b,
                            float* __restrict__ out)
{
    __shared__ float warp_sums[NWARPS];         // 16 floats = 4 x float4

    const int row = blockIdx.x;
    const int tid = threadIdx.x;

    const float* aR = a   + (size_t)row * L;
    const float* bR = b   + (size_t)row * L;
    float*       oR = out + (size_t)row * L;

    // ---- Phase 1: row-sum of a with 256-bit loads ----
    float s0 = 0.f, s1 = 0.f, s2 = 0.f, s3 = 0.f;
    #pragma unroll
    for (int i = 0; i < V8PT; i++) {
        float r[8];
        ldg_v8(aR + (tid + i * THREADS) * 8, r);
        s0 += r[0] + r[4];
        s1 += r[1] + r[5];
        s2 += r[2] + r[6];
        s3 += r[3] + r[7];
    }
    float s = (s0 + s1) + (s2 + s3);

    // warp reduce (xor: full sum in every lane)
    #pragma unroll
    for (int off = 16; off > 0; off >>= 1)
        s += __shfl_xor_sync(0xFFFFFFFFu, s, off);

    if ((tid & 31) == 0) warp_sums[tid >> 5] = s;
    __syncthreads();                             // single barrier

    // Every thread sums the 16 partials (broadcast LDS.128, conflict-free).
    const float4 w0 = *reinterpret_cast<const float4*>(&warp_sums[0]);
    const float4 w1 = *reinterpret_cast<const float4*>(&warp_sums[4]);
    const float4 w2 = *reinterpret_cast<const float4*>(&warp_sums[8]);
    const float4 w3 = *reinterpret_cast<const float4*>(&warp_sums[12]);
    const float scale = (((w0.x + w0.y) + (w0.z + w0.w))
                       + ((w1.x + w1.y) + (w1.z + w1.w)))
                      + (((w2.x + w2.y) + (w2.z + w2.w))
                       + ((w3.x + w3.y) + (w3.z + w3.w)));

    // ---- Phase 2: out = b * scale with 256-bit accesses ----
    #pragma unroll
    for (int i = 0; i < V8PT; i++) {
        const int idx = (tid + i * THREADS) * 8;
        float r[8];
        ldg_v8(bR + idx, r);
        #pragma unroll
        for (int k = 0; k < 8; k++) r[k] *= scale;
        stg_v8(oR + idx, r);
    }
}

extern "C" void kernel_launch(void* const* d_in, const int* in_sizes, int n_in,
                              void* d_out, int out_size)
{
    const float* a = (const float*)d_in[0];
    const float* b = (const float*)d_in[1];
    float* out = (float*)d_out;

    const int rows = in_sizes[0] / L;            // 8192
    outer_product_rowscale<<<rows, THREADS>>>(a, b, out);
}

// round 17
// speedup vs baseline: 1.0173x; 1.0052x over previous
#include <cuda_runtime.h>

// out[n, i] = b[n, i] * sum_j a[n, j],  B = L = 8192, fp32.
// Stream-locality gradient (confirmed monotone 128t<256t<512t): now 1024
// threads/CTA -> 2 CTAs/SM -> only 2 concurrent row-streams per SM.
// Still 64 warps/SM. v8.f32 accesses both phases, plain cached,
// single-barrier reduction.

constexpr int L = 8192;
constexpr int THREADS = 1024;
constexpr int NWARPS = THREADS / 32;            // 32
constexpr int V8_PER_ROW = L / 8;               // 1024 float8 per row
constexpr int V8PT = V8_PER_ROW / THREADS;      // 1 float8 per thread

__device__ __forceinline__ void ldg_v8(const float* p, float r[8]) {
    asm volatile("ld.global.v8.f32 {%0,%1,%2,%3,%4,%5,%6,%7}, [%8];"
                 : "=f"(r[0]), "=f"(r[1]), "=f"(r[2]), "=f"(r[3]),
                   "=f"(r[4]), "=f"(r[5]), "=f"(r[6]), "=f"(r[7])
                 : "l"(p));
}

__device__ __forceinline__ void stg_v8(float* p, const float r[8]) {
    asm volatile("st.global.v8.f32 [%0], {%1,%2,%3,%4,%5,%6,%7,%8};"
                 :: "l"(p),
                    "f"(r[0]), "f"(r[1]), "f"(r[2]), "f"(r[3]),
                    "f"(r[4]), "f"(r[5]), "f"(r[6]), "f"(r[7])
                 : "memory");
}

__global__ __launch_bounds__(THREADS, 2)
void outer_product_rowscale(const float* __restrict__ a,
                            const float* __restrict__ b,
                            float* __restrict__ out)
{
    __shared__ float warp_sums[NWARPS];         // 32 floats = 8 x float4

    const int row = blockIdx.x;
    const int tid = threadIdx.x;

    const float* aR = a   + (size_t)row * L;
    const float* bR = b   + (size_t)row * L;
    float*       oR = out + (size_t)row * L;

    // ---- Phase 1: row-sum of a, one 256-bit load per thread ----
    float r[8];
    ldg_v8(aR + tid * 8, r);
    float s = ((r[0] + r[1]) + (r[2] + r[3]))
            + ((r[4] + r[5]) + (r[6] + r[7]));

    // warp reduce (xor: full sum in every lane)
    #pragma unroll
    for (int off = 16; off > 0; off >>= 1)
        s += __shfl_xor_sync(0xFFFFFFFFu, s, off);

    if ((tid & 31) == 0) warp_sums[tid >> 5] = s;
    __syncthreads();                             // single barrier (32 warps)

    // Every thread sums the 32 partials (broadcast LDS.128, conflict-free).
    float scale = 0.f;
    #pragma unroll
    for (int w = 0; w < NWARPS / 4; w++) {
        const float4 t = *reinterpret_cast<const float4*>(&warp_sums[w * 4]);
        scale += (t.x + t.y) + (t.z + t.w);
    }

    // ---- Phase 2: out = b * scale, one 256-bit load+store per thread ----
    float q[8];
    ldg_v8(bR + tid * 8, q);
    #pragma unroll
    for (int k = 0; k < 8; k++) q[k] *= scale;
    stg_v8(oR + tid * 8, q);
}

extern "C" void kernel_launch(void* const* d_in, const int* in_sizes, int n_in,
                              void* d_out, int out_size)
{
    const float* a = (const float*)d_in[0];
    const float* b = (const float*)d_in[1];
    float* out = (float*)d_out;

    const int rows = in_sizes[0] / L;            // 8192
    outer_product_rowscale<<<rows, THREADS>>>(a, b, out);
}